// round 12
// baseline (speedup 1.0000x reference)
#include <cuda_runtime.h>
#include <cuda_bf16.h>
#include <cstdint>
#include <cstddef>

#define NN 16384
#define HD 64

// ---------------- static device scratch (no runtime allocation) ----------------
__device__ __nv_bfloat16 g_BhiT[HD * NN];          // hr^T hi plane [f][j]
__device__ __nv_bfloat16 g_BloT[HD * NN];          // hr^T lo plane [f][j]
__device__ float         g_rootT[(size_t)HD * NN]; // (b + h @ W_root^T)^T  [f][j]
__device__ float         g_hT[(size_t)HD * NN];    // layer intermediate, transposed [f][j]

// ---------------- helpers ----------------
__device__ __forceinline__ uint32_t smem_u32(const void* p) {
    uint32_t a;
    asm("{ .reg .u64 t; cvta.to.shared.u64 t, %1; cvt.u32.u64 %0, t; }" : "=r"(a) : "l"(p));
    return a;
}
__device__ __forceinline__ void cp16(uint32_t s, const void* g) {
    asm volatile("cp.async.cg.shared.global [%0], [%1], 16;"
                 :: "r"(s), "l"(__cvta_generic_to_global(g)) : "memory");
}
#define CP_COMMIT() asm volatile("cp.async.commit_group;" ::: "memory")

__device__ __forceinline__ uint32_t sw128(uint32_t off) { return off ^ ((off >> 3) & 0x70); }

__device__ __forceinline__ void ldsm_x4(uint32_t addr, uint32_t& r0, uint32_t& r1,
                                        uint32_t& r2, uint32_t& r3) {
    asm volatile("ldmatrix.sync.aligned.m8n8.x4.shared.b16 {%0,%1,%2,%3}, [%4];"
                 : "=r"(r0), "=r"(r1), "=r"(r2), "=r"(r3) : "r"(addr));
}
__device__ __forceinline__ void ldsm_x4_t(uint32_t addr, uint32_t& r0, uint32_t& r1,
                                          uint32_t& r2, uint32_t& r3) {
    asm volatile("ldmatrix.sync.aligned.m8n8.x4.trans.shared.b16 {%0,%1,%2,%3}, [%4];"
                 : "=r"(r0), "=r"(r1), "=r"(r2), "=r"(r3) : "r"(addr));
}

// D += A(16x16 bf16) * B(16x8 bf16), fp32 accumulate
__device__ __forceinline__ void mma16816(float* c, const uint32_t* a, uint32_t b0, uint32_t b1) {
    asm volatile(
        "mma.sync.aligned.m16n8k16.row.col.f32.bf16.bf16.f32 "
        "{%0,%1,%2,%3}, {%4,%5,%6,%7}, {%8,%9}, {%0,%1,%2,%3};"
        : "+f"(c[0]), "+f"(c[1]), "+f"(c[2]), "+f"(c[3])
        : "r"(a[0]), "r"(a[1]), "r"(a[2]), "r"(a[3]), "r"(b0), "r"(b1));
}

// ---------------- kernel 1: layer-0 hr^T planes + rootT from X ----------------
__global__ void __launch_bounds__(256) relroot256_kernel(
    const float* __restrict__ X, const float* __restrict__ Wrel,
    const float* __restrict__ bias, const float* __restrict__ Wroot)
{
    extern __shared__ float sm[];
    const int F = 256;
    float* hs = sm;                      // [64][F+1]
    float* wr = sm + 64 * (F + 1);
    float* wo = wr + 64 * (F + 1);
    int j0 = blockIdx.x * 64;

    for (int idx = threadIdx.x; idx < 64 * F; idx += 256) {
        int r = idx / F, c = idx % F;
        hs[r * (F + 1) + c] = X[(size_t)(j0 + r) * F + c];
        wr[r * (F + 1) + c] = Wrel[r * F + c];
        wo[r * (F + 1) + c] = Wroot[r * F + c];
    }
    __syncthreads();

    int f  = threadIdx.x & 63;
    int jg = threadIdx.x >> 6;           // 0..3 -> 16 nodes each
    float ar[16], ao[16];
#pragma unroll
    for (int k = 0; k < 16; ++k) { ar[k] = 0.f; ao[k] = 0.f; }

    const float* wrf = wr + f * (F + 1);
    const float* wof = wo + f * (F + 1);
    const float* hb  = hs + (jg * 16) * (F + 1);
#pragma unroll 4
    for (int c = 0; c < F; ++c) {
        float a = wrf[c];
        float b = wof[c];
#pragma unroll
        for (int k = 0; k < 16; ++k) {
            float x = hb[k * (F + 1) + c];
            ar[k] = fmaf(a, x, ar[k]);
            ao[k] = fmaf(b, x, ao[k]);
        }
    }
    float bf = bias[f];
#pragma unroll
    for (int k = 0; k < 16; ++k) {
        int j = j0 + jg * 16 + k;
        float v = ar[k];
        __nv_bfloat16 hi = __float2bfloat16(v);
        __nv_bfloat16 lo = __float2bfloat16(v - __bfloat162float(hi));
        g_BhiT[f * NN + j] = hi;
        g_BloT[f * NN + j] = lo;
        g_rootT[(size_t)f * NN + j] = ao[k] + bf;
    }
}

// ---------------- kernel 2: layers 1/2 hr^T planes + rootT from g_hT ----------------
__global__ void __launch_bounds__(256) relroot64T_kernel(
    const float* __restrict__ Wrel, const float* __restrict__ bias,
    const float* __restrict__ Wroot)
{
    extern __shared__ float sm[];
    float* xs = sm;              // [64 c][128 j]
    float* wr = sm + 64 * 128;   // [c][fo]
    float* wo = wr + 64 * 64;
    int tid = threadIdx.x;
    int j0 = blockIdx.x * 128;

    for (int idx = tid; idx < 64 * 128; idx += 256) {
        int c = idx >> 7, jj = idx & 127;
        xs[idx] = g_hT[(size_t)c * NN + j0 + jj];
    }
    for (int idx = tid; idx < 64 * 64; idx += 256) {
        int c = idx >> 6, fo = idx & 63;
        wr[idx] = Wrel[fo * 64 + c];
        wo[idx] = Wroot[fo * 64 + c];
    }
    __syncthreads();

    int jl = tid & 127, half = tid >> 7;
    int fb = half * 32;
    float ar[32], ao[32];
#pragma unroll
    for (int k = 0; k < 32; ++k) { ar[k] = 0.f; ao[k] = 0.f; }

    for (int c = 0; c < 64; ++c) {
        float x = xs[c * 128 + jl];
        const float* wrp = wr + c * 64 + fb;
        const float* wop = wo + c * 64 + fb;
#pragma unroll
        for (int k = 0; k < 32; ++k) {
            ar[k] = fmaf(wrp[k], x, ar[k]);
            ao[k] = fmaf(wop[k], x, ao[k]);
        }
    }
#pragma unroll
    for (int k = 0; k < 32; ++k) {
        int fo = fb + k;
        float v = ar[k];
        __nv_bfloat16 hi = __float2bfloat16(v);
        __nv_bfloat16 lo = __float2bfloat16(v - __bfloat162float(hi));
        g_BhiT[fo * NN + j0 + jl] = hi;
        g_BloT[fo * NN + j0 + jl] = lo;
        g_rootT[(size_t)fo * NN + j0 + jl] = ao[k] + bias[fo];
    }
}

// ---------------- kernel 3: C'[f][i] = hrT @ adj ; out = relu(C' + rootT) ----------------
// CTA: f=64 (full M) x i=128 (N). 8 warps = 4 f-tiles(16) x 2 i-halves(64).
// adj loaded fp32 via LDG -> regs -> split bf16 hi/lo -> STS (swizzled), 3-stage ring.
// A (hrT planes) streamed via cp.async. B fragments via ldmatrix.x4.trans.
#define KT 64
#define NST 3
#define STG 49152u
#define A_HI 0u
#define A_LO 8192u
#define B_HI 16384u
#define B_LO 32768u
#define NITER (NN / KT)                 // 256
#define AGG_SMEM (NST * STG)            // 147456

__device__ __forceinline__ void agg_cpA(uint32_t sb, int st, int t, int tid) {
    uint32_t SB = sb + (uint32_t)st * STG;
    size_t j0 = (size_t)t * KT;
#pragma unroll
    for (int q = tid; q < 512; q += 256) {         // 64 f-rows x 128B per plane
        int row = q >> 3;
        uint32_t sw = sw128((uint32_t)q << 4);
        size_t off = (size_t)row * NN + j0 + (size_t)((q & 7) << 3);
        cp16(SB + A_HI + sw, g_BhiT + off);
        cp16(SB + A_LO + sw, g_BloT + off);
    }
}

__device__ __forceinline__ void agg_convert(uint32_t sb, int st, const float4* vb,
                                            int wid, int lane) {
    uint32_t SB = sb + (uint32_t)st * STG;
#pragma unroll
    for (int q = 0; q < 8; ++q) {
        int j = wid + 8 * q;                       // 0..63
        uint32_t so = (uint32_t)j * 256u
                    + ((((uint32_t)(lane >> 1)) ^ (uint32_t)(j & 7)) << 4)
                    + ((uint32_t)(lane & 1) << 3);
        float4 fv = vb[q];
        uint32_t h01, h23, l01, l23;
        asm("cvt.rn.bf16x2.f32 %0, %1, %2;" : "=r"(h01) : "f"(fv.y), "f"(fv.x));
        asm("cvt.rn.bf16x2.f32 %0, %1, %2;" : "=r"(h23) : "f"(fv.w), "f"(fv.z));
        float hf0 = __uint_as_float(h01 << 16);
        float hf1 = __uint_as_float(h01 & 0xFFFF0000u);
        float hf2 = __uint_as_float(h23 << 16);
        float hf3 = __uint_as_float(h23 & 0xFFFF0000u);
        float l0 = fv.x - hf0, l1 = fv.y - hf1, l2 = fv.z - hf2, l3 = fv.w - hf3;
        asm("cvt.rn.bf16x2.f32 %0, %1, %2;" : "=r"(l01) : "f"(l1), "f"(l0));
        asm("cvt.rn.bf16x2.f32 %0, %1, %2;" : "=r"(l23) : "f"(l3), "f"(l2));
        asm volatile("st.shared.v2.b32 [%0], {%1,%2};"
                     :: "r"(SB + B_HI + so), "r"(h01), "r"(h23) : "memory");
        asm volatile("st.shared.v2.b32 [%0], {%1,%2};"
                     :: "r"(SB + B_LO + so), "r"(l01), "r"(l23) : "memory");
    }
}

__global__ void __launch_bounds__(256, 1) gnn_agg_kernel(
    const float* __restrict__ adj, float* __restrict__ dout, int final_layer)
{
    extern __shared__ char smem[];
    uint32_t sb = smem_u32(smem);
    int tid  = threadIdx.x;
    int lane = tid & 31;
    int wid  = tid >> 5;
    int wi   = wid & 1;                 // i-half (64)
    int wf   = wid >> 1;                // f-tile (16)
    int ibase = blockIdx.x * 128;

    float acc[8][4];
#pragma unroll
    for (int nt = 0; nt < 8; ++nt)
#pragma unroll
        for (int c = 0; c < 4; ++c) acc[nt][c] = 0.f;

    int lrow  = lane & 15;
    int khalf = (lane >= 16) ? 16 : 0;
    int bj_base  = (lane & 7) + ((lane >> 4) << 3);   // k-row within 16
    int nseg_add = (lane >> 3) & 1;                   // n 8-col half

    float4 vb[8];

    // ---- prologue ----
    agg_cpA(sb, 0, 0, tid); CP_COMMIT();
    agg_cpA(sb, 1, 1, tid); CP_COMMIT();
    {
        const float* base = adj + ibase;              // tile 0
#pragma unroll
        for (int q = 0; q < 8; ++q)
            vb[q] = *reinterpret_cast<const float4*>(base + (size_t)(wid + 8 * q) * NN + (lane << 2));
    }
    asm volatile("cp.async.wait_group 0;" ::: "memory");
    agg_convert(sb, 0, vb, wid, lane);
    __syncthreads();

    // ---- mainloop ----
    for (int it = 0; it < NITER; ++it) {
        int s = it % 3;
        if (it + 1 < NITER) {
            const float* base = adj + (size_t)(it + 1) * KT * NN + ibase;
#pragma unroll
            for (int q = 0; q < 8; ++q)
                vb[q] = *reinterpret_cast<const float4*>(base + (size_t)(wid + 8 * q) * NN + (lane << 2));
        }
        {
            uint32_t SB = sb + (uint32_t)s * STG;
#pragma unroll
            for (int k16 = 0; k16 < 4; ++k16) {
                uint32_t aoff = sw128(((uint32_t)(wf * 16 + lrow) << 7)
                                      + ((uint32_t)k16 << 5) + (uint32_t)khalf);
                uint32_t ah[4], al[4];
                ldsm_x4(SB + A_HI + aoff, ah[0], ah[1], ah[2], ah[3]);
                ldsm_x4(SB + A_LO + aoff, al[0], al[1], al[2], al[3]);
                int j = k16 * 16 + bj_base;
                uint32_t rowterm = (uint32_t)j * 256u;
                uint32_t jx = (uint32_t)(j & 7);
#pragma unroll
                for (int ng = 0; ng < 4; ++ng) {
                    uint32_t nseg = (uint32_t)((wi * 64 + ng * 16) >> 3) + (uint32_t)nseg_add;
                    uint32_t boff = rowterm + ((nseg ^ jx) << 4);
                    uint32_t bh0, bh1, bh2, bh3, bl0, bl1, bl2, bl3;
                    ldsm_x4_t(SB + B_HI + boff, bh0, bh1, bh2, bh3);
                    ldsm_x4_t(SB + B_LO + boff, bl0, bl1, bl2, bl3);
                    mma16816(acc[2 * ng],     ah, bh0, bh2);
                    mma16816(acc[2 * ng],     ah, bl0, bl2);
                    mma16816(acc[2 * ng],     al, bh0, bh2);
                    mma16816(acc[2 * ng + 1], ah, bh1, bh3);
                    mma16816(acc[2 * ng + 1], ah, bl1, bl3);
                    mma16816(acc[2 * ng + 1], al, bh1, bh3);
                }
            }
        }
        if (it + 2 < NITER) agg_cpA(sb, (it + 2) % 3, it + 2, tid);
        CP_COMMIT();
        if (it + 1 < NITER) {
            asm volatile("cp.async.wait_group 1;" ::: "memory");
            agg_convert(sb, (it + 1) % 3, vb, wid, lane);
        } else {
            asm volatile("cp.async.wait_group 0;" ::: "memory");
        }
        __syncthreads();
    }

    // ---- epilogue: acc holds C'[f][i] fragments ----
    int r   = lane >> 2;
    int cp2 = (lane & 3) * 2;
    int f0  = wf * 16 + r;
#pragma unroll
    for (int ng = 0; ng < 4; ++ng) {
#pragma unroll
        for (int sub = 0; sub < 2; ++sub) {
            int nt = 2 * ng + sub;
            int i0 = ibase + wi * 64 + ng * 16 + sub * 8 + cp2;
            float v0 = acc[nt][0] + g_rootT[(size_t)f0 * NN + i0];
            float v1 = acc[nt][1] + g_rootT[(size_t)f0 * NN + i0 + 1];
            float v2 = acc[nt][2] + g_rootT[(size_t)(f0 + 8) * NN + i0];
            float v3 = acc[nt][3] + g_rootT[(size_t)(f0 + 8) * NN + i0 + 1];
            v0 = fmaxf(v0, 0.f); v1 = fmaxf(v1, 0.f);
            v2 = fmaxf(v2, 0.f); v3 = fmaxf(v3, 0.f);
            if (final_layer) {
                dout[(size_t)i0 * HD + f0]           = v0;
                dout[(size_t)(i0 + 1) * HD + f0]     = v1;
                dout[(size_t)i0 * HD + f0 + 8]       = v2;
                dout[(size_t)(i0 + 1) * HD + f0 + 8] = v3;
            } else {
                *reinterpret_cast<float2*>(&g_hT[(size_t)f0 * NN + i0])       = make_float2(v0, v1);
                *reinterpret_cast<float2*>(&g_hT[(size_t)(f0 + 8) * NN + i0]) = make_float2(v2, v3);
            }
        }
    }
}

// ---------------- launch ----------------
extern "C" void kernel_launch(void* const* d_in, const int* in_sizes, int n_in,
                              void* d_out, int out_size) {
    const float* X      = (const float*)d_in[0];
    const float* adj    = (const float*)d_in[1];
    const float* Wrel0  = (const float*)d_in[2];
    const float* brel0  = (const float*)d_in[3];
    const float* Wroot0 = (const float*)d_in[4];
    const float* Wrel1  = (const float*)d_in[5];
    const float* brel1  = (const float*)d_in[6];
    const float* Wroot1 = (const float*)d_in[7];
    const float* Wrel2  = (const float*)d_in[8];
    const float* brel2  = (const float*)d_in[9];
    const float* Wroot2 = (const float*)d_in[10];
    float* out = (float*)d_out;

    const int smem256 = 3 * 64 * 257 * (int)sizeof(float);   // 197376
    const int smem64T = (64 * 128 + 2 * 64 * 64) * (int)sizeof(float);  // 65536
    cudaFuncSetAttribute((void*)relroot256_kernel, cudaFuncAttributeMaxDynamicSharedMemorySize, smem256);
    cudaFuncSetAttribute((void*)relroot64T_kernel, cudaFuncAttributeMaxDynamicSharedMemorySize, smem64T);
    cudaFuncSetAttribute((void*)gnn_agg_kernel,    cudaFuncAttributeMaxDynamicSharedMemorySize, (int)AGG_SMEM);

    relroot256_kernel<<<NN / 64, 256, smem256>>>(X, Wrel0, brel0, Wroot0);
    gnn_agg_kernel<<<NN / 128, 256, AGG_SMEM>>>(adj, out, 0);

    relroot64T_kernel<<<NN / 128, 256, smem64T>>>(Wrel1, brel1, Wroot1);
    gnn_agg_kernel<<<NN / 128, 256, AGG_SMEM>>>(adj, out, 0);

    relroot64T_kernel<<<NN / 128, 256, smem64T>>>(Wrel2, brel2, Wroot2);
    gnn_agg_kernel<<<NN / 128, 256, AGG_SMEM>>>(adj, out, 1);
}

// round 13
// speedup vs baseline: 1.2897x; 1.2897x over previous
#include <cuda_runtime.h>
#include <cuda_bf16.h>
#include <cstdint>
#include <cstddef>

#define NN 16384
#define HD 64

// ---------------- static device scratch (no runtime allocation) ----------------
__device__ __nv_bfloat16 g_adj_hi[(size_t)NN * NN];  // adj[j][i] hi plane, native layout
__device__ __nv_bfloat16 g_adj_lo[(size_t)NN * NN];  // residual plane
__device__ __nv_bfloat16 g_BhiT[HD * NN];            // hr^T hi plane [f][j]
__device__ __nv_bfloat16 g_BloT[HD * NN];            // hr^T lo plane [f][j]
__device__ float         g_rootT[(size_t)HD * NN];   // (b + h @ W_root^T)^T  [f][j]
__device__ float         g_hT[(size_t)HD * NN];      // layer intermediate, transposed [f][j]

// ---------------- helpers ----------------
__device__ __forceinline__ uint32_t smem_u32(const void* p) {
    uint32_t a;
    asm("{ .reg .u64 t; cvta.to.shared.u64 t, %1; cvt.u32.u64 %0, t; }" : "=r"(a) : "l"(p));
    return a;
}
__device__ __forceinline__ void cp16(uint32_t s, const void* g) {
    asm volatile("cp.async.cg.shared.global [%0], [%1], 16;"
                 :: "r"(s), "l"(__cvta_generic_to_global(g)) : "memory");
}
#define CP_COMMIT() asm volatile("cp.async.commit_group;" ::: "memory")

__device__ __forceinline__ uint32_t sw128(uint32_t off) { return off ^ ((off >> 3) & 0x70); }

__device__ __forceinline__ void ldsm_x4(uint32_t addr, uint32_t& r0, uint32_t& r1,
                                        uint32_t& r2, uint32_t& r3) {
    asm volatile("ldmatrix.sync.aligned.m8n8.x4.shared.b16 {%0,%1,%2,%3}, [%4];"
                 : "=r"(r0), "=r"(r1), "=r"(r2), "=r"(r3) : "r"(addr));
}
__device__ __forceinline__ void ldsm_x4_t(uint32_t addr, uint32_t& r0, uint32_t& r1,
                                          uint32_t& r2, uint32_t& r3) {
    asm volatile("ldmatrix.sync.aligned.m8n8.x4.trans.shared.b16 {%0,%1,%2,%3}, [%4];"
                 : "=r"(r0), "=r"(r1), "=r"(r2), "=r"(r3) : "r"(addr));
}

// D += A(16x16 bf16) * B(16x8 bf16), fp32 accumulate
__device__ __forceinline__ void mma16816(float* c, const uint32_t* a, uint32_t b0, uint32_t b1) {
    asm volatile(
        "mma.sync.aligned.m16n8k16.row.col.f32.bf16.bf16.f32 "
        "{%0,%1,%2,%3}, {%4,%5,%6,%7}, {%8,%9}, {%0,%1,%2,%3};"
        : "+f"(c[0]), "+f"(c[1]), "+f"(c[2]), "+f"(c[3])
        : "r"(a[0]), "r"(a[1]), "r"(a[2]), "r"(a[3]), "r"(b0), "r"(b1));
}

__device__ __forceinline__ void split2(float x, float y, uint32_t& h, uint32_t& l) {
    asm("cvt.rn.bf16x2.f32 %0, %1, %2;" : "=r"(h) : "f"(y), "f"(x));
    float hf0 = __uint_as_float(h << 16);
    float hf1 = __uint_as_float(h & 0xFFFF0000u);
    float l0 = x - hf0, l1 = y - hf1;
    asm("cvt.rn.bf16x2.f32 %0, %1, %2;" : "=r"(l) : "f"(l1), "f"(l0));
}

// ---------------- kernel 0: split adj fp32 -> bf16 hi/lo planes (native layout) ----------------
__global__ void __launch_bounds__(256) split_kernel(const float* __restrict__ adj) {
    size_t base = ((size_t)blockIdx.x * 256 + threadIdx.x) * 8;
    float4 v0 = *reinterpret_cast<const float4*>(adj + base);
    float4 v1 = *reinterpret_cast<const float4*>(adj + base + 4);
    uint32_t h0, h1, h2, h3, l0, l1, l2, l3;
    split2(v0.x, v0.y, h0, l0);
    split2(v0.z, v0.w, h1, l1);
    split2(v1.x, v1.y, h2, l2);
    split2(v1.z, v1.w, h3, l3);
    *reinterpret_cast<uint4*>(g_adj_hi + base) = make_uint4(h0, h1, h2, h3);
    *reinterpret_cast<uint4*>(g_adj_lo + base) = make_uint4(l0, l1, l2, l3);
}

// ---------------- kernel 1: layer-0 hr^T planes + rootT from X ----------------
__global__ void __launch_bounds__(256) relroot256_kernel(
    const float* __restrict__ X, const float* __restrict__ Wrel,
    const float* __restrict__ bias, const float* __restrict__ Wroot)
{
    extern __shared__ float sm[];
    const int F = 256;
    float* hs = sm;                      // [64][F+1]
    float* wr = sm + 64 * (F + 1);
    float* wo = wr + 64 * (F + 1);
    int j0 = blockIdx.x * 64;

    for (int idx = threadIdx.x; idx < 64 * F; idx += 256) {
        int r = idx / F, c = idx % F;
        hs[r * (F + 1) + c] = X[(size_t)(j0 + r) * F + c];
        wr[r * (F + 1) + c] = Wrel[r * F + c];
        wo[r * (F + 1) + c] = Wroot[r * F + c];
    }
    __syncthreads();

    int f  = threadIdx.x & 63;
    int jg = threadIdx.x >> 6;           // 0..3 -> 16 nodes each
    float ar[16], ao[16];
#pragma unroll
    for (int k = 0; k < 16; ++k) { ar[k] = 0.f; ao[k] = 0.f; }

    const float* wrf = wr + f * (F + 1);
    const float* wof = wo + f * (F + 1);
    const float* hb  = hs + (jg * 16) * (F + 1);
#pragma unroll 4
    for (int c = 0; c < F; ++c) {
        float a = wrf[c];
        float b = wof[c];
#pragma unroll
        for (int k = 0; k < 16; ++k) {
            float x = hb[k * (F + 1) + c];
            ar[k] = fmaf(a, x, ar[k]);
            ao[k] = fmaf(b, x, ao[k]);
        }
    }
    float bf = bias[f];
#pragma unroll
    for (int k = 0; k < 16; ++k) {
        int j = j0 + jg * 16 + k;
        float v = ar[k];
        __nv_bfloat16 hi = __float2bfloat16(v);
        __nv_bfloat16 lo = __float2bfloat16(v - __bfloat162float(hi));
        g_BhiT[f * NN + j] = hi;
        g_BloT[f * NN + j] = lo;
        g_rootT[(size_t)f * NN + j] = ao[k] + bf;
    }
}

// ---------------- kernel 2: layers 1/2 hr^T planes + rootT from g_hT ----------------
__global__ void __launch_bounds__(256) relroot64T_kernel(
    const float* __restrict__ Wrel, const float* __restrict__ bias,
    const float* __restrict__ Wroot)
{
    extern __shared__ float sm[];
    float* xs = sm;              // [64 c][128 j]
    float* wr = sm + 64 * 128;   // [c][fo]
    float* wo = wr + 64 * 64;
    int tid = threadIdx.x;
    int j0 = blockIdx.x * 128;

    for (int idx = tid; idx < 64 * 128; idx += 256) {
        int c = idx >> 7, jj = idx & 127;
        xs[idx] = g_hT[(size_t)c * NN + j0 + jj];
    }
    for (int idx = tid; idx < 64 * 64; idx += 256) {
        int c = idx >> 6, fo = idx & 63;
        wr[idx] = Wrel[fo * 64 + c];
        wo[idx] = Wroot[fo * 64 + c];
    }
    __syncthreads();

    int jl = tid & 127, half = tid >> 7;
    int fb = half * 32;
    float ar[32], ao[32];
#pragma unroll
    for (int k = 0; k < 32; ++k) { ar[k] = 0.f; ao[k] = 0.f; }

    for (int c = 0; c < 64; ++c) {
        float x = xs[c * 128 + jl];
        const float* wrp = wr + c * 64 + fb;
        const float* wop = wo + c * 64 + fb;
#pragma unroll
        for (int k = 0; k < 32; ++k) {
            ar[k] = fmaf(wrp[k], x, ar[k]);
            ao[k] = fmaf(wop[k], x, ao[k]);
        }
    }
#pragma unroll
    for (int k = 0; k < 32; ++k) {
        int fo = fb + k;
        float v = ar[k];
        __nv_bfloat16 hi = __float2bfloat16(v);
        __nv_bfloat16 lo = __float2bfloat16(v - __bfloat162float(hi));
        g_BhiT[fo * NN + j0 + jl] = hi;
        g_BloT[fo * NN + j0 + jl] = lo;
        g_rootT[(size_t)fo * NN + j0 + jl] = ao[k] + bias[fo];
    }
}

// ---------------- kernel 3: C'[f][i] = hrT @ adj ; out = relu(C' + rootT) ----------------
// CTA: f=64 (M) x i=128 (N). 8 warps = 4 f-tiles(16) x 2 i-halves(64).
// All operands stream via cp.async from prebuilt bf16 planes. 4-stage ring, 1 sync/iter.
#define KT 64
#define NST 4
#define STG 49152u
#define A_HI 0u
#define A_LO 8192u
#define B_HI 16384u
#define B_LO 32768u
#define NITER (NN / KT)                 // 256
#define AGG_SMEM (NST * STG)            // 196608

__device__ __forceinline__ void fill_stage(uint32_t sb, int st, int t, int tid, int ibase) {
    uint32_t SB = sb + (uint32_t)st * STG;
    size_t j0 = (size_t)t * KT;
    // A planes (hr^T): 64 f-rows x 128B (64 bf16 of k), SW128 swizzled
#pragma unroll
    for (int q = tid; q < 512; q += 256) {
        int f = q >> 3;
        uint32_t dst = sw128((uint32_t)q << 4);
        size_t off = (size_t)f * NN + j0 + (size_t)((q & 7) << 3);
        cp16(SB + A_HI + dst, g_BhiT + off);
        cp16(SB + A_LO + dst, g_BloT + off);
    }
    // B planes (adj native): 64 j-rows x 256B (128 bf16 of i), chunk-XOR swizzle
#pragma unroll
    for (int q = tid; q < 1024; q += 256) {
        int j = q >> 4, c = q & 15;
        uint32_t dst = (uint32_t)j * 256u + (((uint32_t)(c ^ (j & 7))) << 4);
        size_t off = (size_t)(j0 + j) * NN + ibase + (size_t)(c << 3);
        cp16(SB + B_HI + dst, g_adj_hi + off);
        cp16(SB + B_LO + dst, g_adj_lo + off);
    }
}

__global__ void __launch_bounds__(256, 1) gnn_agg_kernel(float* __restrict__ dout, int final_layer) {
    extern __shared__ char smem[];
    uint32_t sb = smem_u32(smem);
    int tid  = threadIdx.x;
    int lane = tid & 31;
    int wid  = tid >> 5;
    int wi   = wid & 1;                 // i-half (64)
    int wf   = wid >> 1;                // f-tile (16)
    int ibase = blockIdx.x * 128;

    float acc[8][4];
#pragma unroll
    for (int nt = 0; nt < 8; ++nt)
#pragma unroll
        for (int c = 0; c < 4; ++c) acc[nt][c] = 0.f;

    int lrow  = lane & 15;
    int khalf = (lane >= 16) ? 16 : 0;
    int bj_base  = (lane & 7) + ((lane >> 4) << 3);   // k-row within 16
    int nseg_add = (lane >> 3) & 1;                   // n 8-col half

    // prologue: fill stages 0..2
    for (int p = 0; p < NST - 1; ++p) { fill_stage(sb, p, p, tid, ibase); CP_COMMIT(); }

    for (int it = 0; it < NITER; ++it) {
        asm volatile("cp.async.wait_group 2;" ::: "memory");   // tile `it` landed
        __syncthreads();                                       // visible to all; stage (it-1)&3 free

        int nf = it + NST - 1;
        if (nf < NITER) fill_stage(sb, nf & 3, nf, tid, ibase);
        CP_COMMIT();                                           // exactly one group per iter

        uint32_t SB = sb + (uint32_t)(it & 3) * STG;
#pragma unroll
        for (int k16 = 0; k16 < 4; ++k16) {
            uint32_t aoff = sw128(((uint32_t)(wf * 16 + lrow) << 7)
                                  + ((uint32_t)k16 << 5) + (uint32_t)khalf);
            uint32_t ah[4], al[4];
            ldsm_x4(SB + A_HI + aoff, ah[0], ah[1], ah[2], ah[3]);
            ldsm_x4(SB + A_LO + aoff, al[0], al[1], al[2], al[3]);
            int j = k16 * 16 + bj_base;
            uint32_t rowterm = (uint32_t)j * 256u;
            uint32_t jx = (uint32_t)(j & 7);
#pragma unroll
            for (int ng = 0; ng < 4; ++ng) {
                uint32_t nseg = (uint32_t)((wi * 64 + ng * 16) >> 3) + (uint32_t)nseg_add;
                uint32_t boff = rowterm + ((nseg ^ jx) << 4);
                uint32_t bh0, bh1, bh2, bh3, bl0, bl1, bl2, bl3;
                ldsm_x4_t(SB + B_HI + boff, bh0, bh1, bh2, bh3);
                ldsm_x4_t(SB + B_LO + boff, bl0, bl1, bl2, bl3);
                mma16816(acc[2 * ng],     ah, bh0, bh2);
                mma16816(acc[2 * ng],     ah, bl0, bl2);
                mma16816(acc[2 * ng],     al, bh0, bh2);
                mma16816(acc[2 * ng + 1], ah, bh1, bh3);
                mma16816(acc[2 * ng + 1], ah, bl1, bl3);
                mma16816(acc[2 * ng + 1], al, bh1, bh3);
            }
        }
    }
    asm volatile("cp.async.wait_group 0;" ::: "memory");

    // ---- epilogue: acc holds C'[f][i] fragments ----
    int r   = lane >> 2;
    int cp2 = (lane & 3) * 2;
    int f0  = wf * 16 + r;
#pragma unroll
    for (int ng = 0; ng < 4; ++ng) {
#pragma unroll
        for (int sub = 0; sub < 2; ++sub) {
            int nt = 2 * ng + sub;
            int i0 = ibase + wi * 64 + ng * 16 + sub * 8 + cp2;
            float v0 = acc[nt][0] + g_rootT[(size_t)f0 * NN + i0];
            float v1 = acc[nt][1] + g_rootT[(size_t)f0 * NN + i0 + 1];
            float v2 = acc[nt][2] + g_rootT[(size_t)(f0 + 8) * NN + i0];
            float v3 = acc[nt][3] + g_rootT[(size_t)(f0 + 8) * NN + i0 + 1];
            v0 = fmaxf(v0, 0.f); v1 = fmaxf(v1, 0.f);
            v2 = fmaxf(v2, 0.f); v3 = fmaxf(v3, 0.f);
            if (final_layer) {
                dout[(size_t)i0 * HD + f0]           = v0;
                dout[(size_t)(i0 + 1) * HD + f0]     = v1;
                dout[(size_t)i0 * HD + f0 + 8]       = v2;
                dout[(size_t)(i0 + 1) * HD + f0 + 8] = v3;
            } else {
                *reinterpret_cast<float2*>(&g_hT[(size_t)f0 * NN + i0])       = make_float2(v0, v1);
                *reinterpret_cast<float2*>(&g_hT[(size_t)(f0 + 8) * NN + i0]) = make_float2(v2, v3);
            }
        }
    }
}

// ---------------- launch ----------------
extern "C" void kernel_launch(void* const* d_in, const int* in_sizes, int n_in,
                              void* d_out, int out_size) {
    const float* X      = (const float*)d_in[0];
    const float* adj    = (const float*)d_in[1];
    const float* Wrel0  = (const float*)d_in[2];
    const float* brel0  = (const float*)d_in[3];
    const float* Wroot0 = (const float*)d_in[4];
    const float* Wrel1  = (const float*)d_in[5];
    const float* brel1  = (const float*)d_in[6];
    const float* Wroot1 = (const float*)d_in[7];
    const float* Wrel2  = (const float*)d_in[8];
    const float* brel2  = (const float*)d_in[9];
    const float* Wroot2 = (const float*)d_in[10];
    float* out = (float*)d_out;

    const int smem256 = 3 * 64 * 257 * (int)sizeof(float);              // 197376
    const int smem64T = (64 * 128 + 2 * 64 * 64) * (int)sizeof(float);  // 65536
    cudaFuncSetAttribute((void*)relroot256_kernel, cudaFuncAttributeMaxDynamicSharedMemorySize, smem256);
    cudaFuncSetAttribute((void*)relroot64T_kernel, cudaFuncAttributeMaxDynamicSharedMemorySize, smem64T);
    cudaFuncSetAttribute((void*)gnn_agg_kernel,    cudaFuncAttributeMaxDynamicSharedMemorySize, (int)AGG_SMEM);

    split_kernel<<<(int)(((size_t)NN * NN) / (256 * 8)), 256>>>(adj);

    relroot256_kernel<<<NN / 64, 256, smem256>>>(X, Wrel0, brel0, Wroot0);
    gnn_agg_kernel<<<NN / 128, 256, AGG_SMEM>>>(out, 0);

    relroot64T_kernel<<<NN / 128, 256, smem64T>>>(Wrel1, brel1, Wroot1);
    gnn_agg_kernel<<<NN / 128, 256, AGG_SMEM>>>(out, 0);

    relroot64T_kernel<<<NN / 128, 256, smem64T>>>(Wrel2, brel2, Wroot2);
    gnn_agg_kernel<<<NN / 128, 256, AGG_SMEM>>>(out, 1);
}